// round 2
// baseline (speedup 1.0000x reference)
#include <cuda_runtime.h>

// NARX RNN, D=4, HID=64, NX=16, NT=512, NGRID=2048, NY=1.
// TWO threads per (t,grid) sequence, split by hidden index k:
//   lane parity p owns k in [32p, 32p+32).
// Each thread keeps a full 64-wide partial accumulator (32 f32x2 pairs)
// and rank-1 updates it with its own k's; the pair exchanges partial sums
// once per step via shfl_xor, then each tanh's only its own 32 values.
// Peak live regs ~125 -> fits launch_bounds(128,3) cap of 168, no spill.

typedef unsigned long long u64;

#define NG_LOG2 11
#define NXF 16
#define DLY 4

__device__ __forceinline__ u64 fma2(u64 a, u64 b, u64 c) {
    u64 d;
    asm("fma.rn.f32x2 %0, %1, %2, %3;" : "=l"(d) : "l"(a), "l"(b), "l"(c));
    return d;
}
__device__ __forceinline__ u64 add2(u64 a, u64 b) {
    u64 d;
    asm("add.rn.f32x2 %0, %1, %2;" : "=l"(d) : "l"(a), "l"(b));
    return d;
}
__device__ __forceinline__ u64 pack2(float x) {
    u64 r;
    asm("mov.b64 %0, {%1, %1};" : "=l"(r) : "f"(x));
    return r;
}
__device__ __forceinline__ u64 pack2b(float a, float b) {
    u64 r;
    asm("mov.b64 %0, {%1, %2};" : "=l"(r) : "f"(a), "f"(b));
    return r;
}
__device__ __forceinline__ void unpack2(u64 v, float& lo, float& hi) {
    asm("mov.b64 {%0, %1}, %2;" : "=f"(lo), "=f"(hi) : "l"(v));
}

__global__ __launch_bounds__(128, 3)
void narx_kernel(const float* __restrict__ x,
                 const float* __restrict__ W_in,
                 const float* __restrict__ b_in,
                 const float* __restrict__ W_xh,
                 const float* __restrict__ W_hh,
                 const float* __restrict__ b_h,
                 const float* __restrict__ W_out,
                 const float* __restrict__ b_out,
                 float* __restrict__ out)
{
    // u64 views of row-major fp32 weights: (W[k][2j], W[k][2j+1]) adjacent.
    __shared__ u64 sWin[16 * 32];   // [i][kp]   4 KB
    __shared__ u64 sWxh[64 * 32];   // [k][jp]  16 KB
    __shared__ u64 sWhh[64 * 32];   // [k][jp]  16 KB
    __shared__ u64 sBin[32];
    __shared__ u64 sBh[32];
    __shared__ float sWout[64];
    __shared__ float sBout;

    const int tid = threadIdx.x;
    {
        const u64* g1 = (const u64*)W_in;
        for (int i = tid; i < 512; i += 128) sWin[i] = g1[i];
        const u64* g2 = (const u64*)W_xh;
        const u64* g3 = (const u64*)W_hh;
        for (int i = tid; i < 2048; i += 128) { sWxh[i] = g2[i]; sWhh[i] = g3[i]; }
        if (tid < 32) { sBin[tid] = ((const u64*)b_in)[tid]; sBh[tid] = ((const u64*)b_h)[tid]; }
        if (tid < 64) sWout[tid] = W_out[tid];
        if (tid == 0) sBout = b_out[0];
    }
    __syncthreads();

    const int tg = blockIdx.x * 128 + tid;   // global thread id (2 per seq)
    const int n  = tg >> 1;                  // sequence id = t*NG + g
    const int p  = tg & 1;                   // pair parity: owns k in [32p,32p+32)
    const int g  = n & ((1 << NG_LOG2) - 1);
    const int t  = n >> NG_LOG2;
    // t is uniform within a block (block covers 64 consecutive n, 2048 | 64*b)
    if (t < DLY) { if (p == 0) out[n] = 0.0f; return; }

    u64 h[16];    // own 32 hidden values as 16 f32 pairs (k = 32p + 2*hp (+1))
    u64 acc[32];  // full-width partial accumulator (64 floats)

    for (int d = 0; d < DLY; d++) {
        // ---- load lag-window input x[t-D+d, g, :] ----
        const float4* xr =
            (const float4*)(x + (size_t)((((t - DLY + d) << NG_LOG2) | g)) * NXF);
        float4 xv0 = xr[0], xv1 = xr[1], xv2 = xr[2], xv3 = xr[3];
        float xs[16] = { xv0.x, xv0.y, xv0.z, xv0.w,
                         xv1.x, xv1.y, xv1.z, xv1.w,
                         xv2.x, xv2.y, xv2.z, xv2.w,
                         xv3.x, xv3.y, xv3.z, xv3.w };

        // bias b_h counted once per pair (parity 0 thread)
        #pragma unroll
        for (int jp = 0; jp < 32; jp++) acc[jp] = (p == 0) ? sBh[jp] : 0ull;

        // ---- phase 1: u[k] = relu(b_in + x.W_in[:,k]) for OWN k's, fused
        //      with rank-1 update acc[:] += u[k] * W_xh[k,:] ----
        #pragma unroll 4
        for (int kp = 0; kp < 16; kp++) {
            const int kg = p * 16 + kp;          // pair index -> k = 2kg, 2kg+1
            u64 up = sBin[kg];
            #pragma unroll
            for (int i = 0; i < 16; i++)
                up = fma2(pack2(xs[i]), sWin[i * 32 + kg], up);
            float ul, uh; unpack2(up, ul, uh);
            ul = fmaxf(ul, 0.0f); uh = fmaxf(uh, 0.0f);
            const u64 pl = pack2(ul), ph = pack2(uh);
            const u64* w0 = &sWxh[(2 * kg) * 32];
            #pragma unroll
            for (int jp = 0; jp < 32; jp++) {
                acc[jp] = fma2(pl, w0[jp],      acc[jp]);
                acc[jp] = fma2(ph, w0[32 + jp], acc[jp]);
            }
        }

        // ---- phase 2: acc[:] += h[k] * W_hh[k,:] for OWN k's (h==0 at d==0) ----
        if (d > 0) {
            #pragma unroll 4
            for (int hp = 0; hp < 16; hp++) {
                float a, b; unpack2(h[hp], a, b);
                const u64 pl = pack2(a), ph = pack2(b);
                const int k0 = 32 * p + 2 * hp;
                const u64* w0 = &sWhh[k0 * 32];
                #pragma unroll
                for (int jp = 0; jp < 32; jp++) {
                    acc[jp] = fma2(pl, w0[jp],      acc[jp]);
                    acc[jp] = fma2(ph, w0[32 + jp], acc[jp]);
                }
            }
        }

        // ---- pair exchange: send my partial over partner's half, receive
        //      partner's partial over MY half; sum; tanh own 32 values ----
        #pragma unroll
        for (int jpl = 0; jpl < 16; jpl++) {
            const u64 v = acc[(1 - p) * 16 + jpl];             // partner's half
            const u64 r = __shfl_xor_sync(0xFFFFFFFFu, v, 1);  // their partial on mine
            const u64 s = add2(acc[p * 16 + jpl], r);
            float a, b; unpack2(s, a, b);
            h[jpl] = pack2b(tanhf(a), tanhf(b));
        }
    }

    // ---- y = h . W_out + b_out  (partial over own k, pair-reduce) ----
    float y = (p == 0) ? sBout : 0.0f;
    #pragma unroll
    for (int hp = 0; hp < 16; hp++) {
        float a, b; unpack2(h[hp], a, b);
        const int k0 = 32 * p + 2 * hp;
        y = fmaf(a, sWout[k0],     y);
        y = fmaf(b, sWout[k0 + 1], y);
    }
    y += __shfl_xor_sync(0xFFFFFFFFu, y, 1);
    if (p == 0) out[n] = y;
}

extern "C" void kernel_launch(void* const* d_in, const int* in_sizes, int n_in,
                              void* d_out, int out_size) {
    const float* x     = (const float*)d_in[0];
    const float* W_in  = (const float*)d_in[1];
    const float* b_in  = (const float*)d_in[2];
    const float* W_xh  = (const float*)d_in[3];
    const float* W_hh  = (const float*)d_in[4];
    const float* b_h   = (const float*)d_in[5];
    const float* W_out = (const float*)d_in[6];
    const float* b_out = (const float*)d_in[7];

    const int total_threads = 2 * 512 * 2048;   // 2 per sequence
    narx_kernel<<<total_threads / 128, 128>>>(x, W_in, b_in, W_xh, W_hh, b_h,
                                              W_out, b_out, (float*)d_out);
    (void)in_sizes; (void)n_in; (void)out_size;
}

// round 3
// speedup vs baseline: 5.3632x; 5.3632x over previous
#include <cuda_runtime.h>

// NARX RNN, D=4, HID=64, NX=16, NT=512, NGRID=2048, NY=1.
//
// Kernel 1 (u_kernel): U[tau][k][G] = relu(x[tau]·W_in + b_in), packed as
//   f32x2 over adjacent-g pairs (g=2G, 2G+1), in a __device__ scratch array.
//   Removes the 4x cross-t recompute of u and all x-gather from the hot loop.
//
// Kernel 2 (narx_main): f32x2 lanes = SEQUENCE PAIR (not j-pair), so weights
//   are scalar LDS.32 broadcasts (1 crossbar cycle) splatted via ALU mov and
//   reused across S=4 units per thread -> 8x less weight-crossbar per FMA
//   than R2. Group of 8 threads owns j = jt (mod 8); h lives in padded SMEM,
//   synchronized with __syncwarp only (no block barriers in the hot loop).

typedef unsigned long long u64;

#define NT   512
#define NG   2048
#define NGP  1024      // g-pairs
#define NXF  16
#define DLY  4

__device__ u64 g_U[(size_t)NT * 64 * NGP];   // 268 MB scratch: [tau][k][G]

__device__ __forceinline__ u64 fma2(u64 a, u64 b, u64 c) {
    u64 d; asm("fma.rn.f32x2 %0, %1, %2, %3;" : "=l"(d) : "l"(a), "l"(b), "l"(c));
    return d;
}
__device__ __forceinline__ u64 add2(u64 a, u64 b) {
    u64 d; asm("add.rn.f32x2 %0, %1, %2;" : "=l"(d) : "l"(a), "l"(b));
    return d;
}
__device__ __forceinline__ u64 pack2(float x) {
    u64 r; asm("mov.b64 %0, {%1, %1};" : "=l"(r) : "f"(x));
    return r;
}
__device__ __forceinline__ u64 pack2b(float a, float b) {
    u64 r; asm("mov.b64 %0, {%1, %2};" : "=l"(r) : "f"(a), "f"(b));
    return r;
}
__device__ __forceinline__ void unpack2(u64 v, float& lo, float& hi) {
    asm("mov.b64 {%0, %1}, %2;" : "=f"(lo), "=f"(hi) : "l"(v));
}
// tanh(x) = 1 - 2/(exp(2x)+1); MUFU.EX2 + MUFU.RCP, ~1e-6 rel err, saturates
// correctly at +/-1 for large |x| (exp -> inf or 0).
__device__ __forceinline__ float tanh_fast(float v) {
    float e = __expf(2.0f * v);
    return 1.0f - __fdividef(2.0f, e + 1.0f);
}

// -------------------- kernel 1: precompute packed U --------------------
__global__ __launch_bounds__(256)
void u_kernel(const float* __restrict__ x,
              const float* __restrict__ W_in,
              const float* __restrict__ b_in)
{
    __shared__ float sW[NXF * 64];
    __shared__ float sB[64];
    const int tid = threadIdx.x;
    for (int i = tid; i < NXF * 64; i += 256) sW[i] = W_in[i];
    if (tid < 64) sB[tid] = b_in[tid];
    __syncthreads();

    const int b   = blockIdx.x;          // 512*4 blocks
    const int tau = b >> 2;
    const int G   = ((b & 3) << 8) + tid;

    const float4* xr = (const float4*)(x + ((size_t)tau * NG + 2 * G) * NXF);
    float4 ra[4] = { xr[0], xr[1], xr[2], xr[3] };   // row g=2G
    float4 rb[4] = { xr[4], xr[5], xr[6], xr[7] };   // row g=2G+1
    const float* fa = (const float*)ra;
    const float* fb = (const float*)rb;
    u64 x2[16];
    #pragma unroll
    for (int i = 0; i < 16; i++) x2[i] = pack2b(fa[i], fb[i]);

    u64* dst = g_U + (size_t)tau * 64 * NGP + G;
    #pragma unroll 8
    for (int k = 0; k < 64; k++) {
        u64 a = pack2(sB[k]);
        #pragma unroll
        for (int i = 0; i < 16; i++)
            a = fma2(x2[i], pack2(sW[i * 64 + k]), a);
        float lo, hi; unpack2(a, lo, hi);
        dst[(size_t)k * NGP] = pack2b(fmaxf(lo, 0.0f), fmaxf(hi, 0.0f));
    }
}

// -------------------- kernel 2: recurrence --------------------
// Dynamic smem layout (bytes):
//   [0, 34304)       sH   : u64 [64 units][67]   (padded vs bank conflicts)
//   [34304, 50688)   sXh  : float [64][64]  W_xh
//   [50688, 67072)   sHh  : float [64][64]  W_hh
//   [67072, 67328)   sBh  : float [64]
//   [67328, 67584)   sWo  : float [64]
//   [67584, 67588)   sBo  : float
#define SMEM_BYTES 67592

__global__ __launch_bounds__(128, 3)
void narx_main(const float* __restrict__ W_xh, const float* __restrict__ W_hh,
               const float* __restrict__ b_h,  const float* __restrict__ W_out,
               const float* __restrict__ b_out, float* __restrict__ out)
{
    extern __shared__ char smem[];
    u64*   sH  = (u64*)smem;
    float* sXh = (float*)(smem + 34304);
    float* sHh = (float*)(smem + 50688);
    float* sBh = (float*)(smem + 67072);
    float* sWo = (float*)(smem + 67328);
    float* sBo = (float*)(smem + 67584);

    const int tid = threadIdx.x;
    for (int i = tid; i < 4096; i += 128) { sXh[i] = W_xh[i]; sHh[i] = W_hh[i]; }
    if (tid < 64) { sBh[tid] = b_h[tid]; sWo[tid] = W_out[tid]; }
    if (tid == 0) sBo[0] = b_out[0];
    __syncthreads();

    const int b   = blockIdx.x;          // 508*16 blocks
    const int t   = DLY + (b >> 4);      // uniform per block
    const int G0  = (b & 15) << 6;       // 64 units per block
    const int jt  = tid & 7;             // owns j == jt (mod 8)
    const int grp = tid >> 3;            // 0..15
    const int ub  = grp << 2;            // this group's unit base (S=4 units)

    u64* hr0 = sH + (size_t)(ub + 0) * 67;
    u64* hr1 = sH + (size_t)(ub + 1) * 67;
    u64* hr2 = sH + (size_t)(ub + 2) * 67;
    u64* hr3 = sH + (size_t)(ub + 3) * 67;

    u64 acc[4][8];
    u64 y2[4] = {0ull, 0ull, 0ull, 0ull};

    for (int d = 0; d < DLY; d++) {
        const int tau = t - DLY + d;

        #pragma unroll
        for (int jj = 0; jj < 8; jj++) {
            const u64 bb = pack2(sBh[(jj << 3) + jt]);
            acc[0][jj] = bb; acc[1][jj] = bb; acc[2][jj] = bb; acc[3][jj] = bb;
        }

        // ---- phase 1: acc[j] += sum_k u[k] * W_xh[k][j]  (u from gmem) ----
        {
            const u64* Up = g_U + (size_t)tau * 64 * NGP + (G0 + ub);
            const float* wp = sXh + jt;
            #pragma unroll 1
            for (int k0 = 0; k0 < 64; k0 += 8) {
                #pragma unroll
                for (int kk = 0; kk < 8; kk++) {
                    const ulonglong2 pa = *(const ulonglong2*)(Up + (size_t)kk * NGP);
                    const ulonglong2 pb = *(const ulonglong2*)(Up + (size_t)kk * NGP + 2);
                    const float* w = wp + (kk << 6);
                    #pragma unroll
                    for (int jj = 0; jj < 8; jj++) {
                        const u64 w2 = pack2(w[jj << 3]);
                        acc[0][jj] = fma2(pa.x, w2, acc[0][jj]);
                        acc[1][jj] = fma2(pa.y, w2, acc[1][jj]);
                        acc[2][jj] = fma2(pb.x, w2, acc[2][jj]);
                        acc[3][jj] = fma2(pb.y, w2, acc[3][jj]);
                    }
                }
                Up += 8 * NGP;
                wp += 8 * 64;
            }
        }

        // ---- phase 2: acc[j] += sum_k h[k] * W_hh[k][j]  (h from smem) ----
        if (d) {
            const float* wp = sHh + jt;
            #pragma unroll 1
            for (int k0 = 0; k0 < 64; k0 += 8) {
                #pragma unroll
                for (int kk = 0; kk < 8; kk++) {
                    const int k = k0 + kk;
                    const u64 h0 = hr0[k], h1 = hr1[k], h2 = hr2[k], h3 = hr3[k];
                    const float* w = wp + (kk << 6);
                    #pragma unroll
                    for (int jj = 0; jj < 8; jj++) {
                        const u64 w2 = pack2(w[jj << 3]);
                        acc[0][jj] = fma2(h0, w2, acc[0][jj]);
                        acc[1][jj] = fma2(h1, w2, acc[1][jj]);
                        acc[2][jj] = fma2(h2, w2, acc[2][jj]);
                        acc[3][jj] = fma2(h3, w2, acc[3][jj]);
                    }
                }
                wp += 8 * 64;
            }
        }

        __syncwarp();   // group done READING old h before overwriting

        if (d < DLY - 1) {
            #pragma unroll
            for (int s = 0; s < 4; s++) {
                u64* hrs = sH + (size_t)(ub + s) * 67;
                #pragma unroll
                for (int jj = 0; jj < 8; jj++) {
                    float a, c; unpack2(acc[s][jj], a, c);
                    hrs[(jj << 3) + jt] = pack2b(tanh_fast(a), tanh_fast(c));
                }
            }
        } else {
            // last step: fold tanh(h) straight into the output dot product
            #pragma unroll
            for (int s = 0; s < 4; s++) {
                #pragma unroll
                for (int jj = 0; jj < 8; jj++) {
                    float a, c; unpack2(acc[s][jj], a, c);
                    const u64 hp = pack2b(tanh_fast(a), tanh_fast(c));
                    y2[s] = fma2(hp, pack2(sWo[(jj << 3) + jt]), y2[s]);
                }
            }
        }
        __syncwarp();   // new h visible before next step's phase 2
    }

    // reduce y over the 8 jt lanes of the group, then store 2 floats per unit
    #pragma unroll
    for (int s = 0; s < 4; s++) {
        u64 v = y2[s];
        v = add2(v, __shfl_xor_sync(0xFFFFFFFFu, v, 1));
        v = add2(v, __shfl_xor_sync(0xFFFFFFFFu, v, 2));
        v = add2(v, __shfl_xor_sync(0xFFFFFFFFu, v, 4));
        y2[s] = v;
    }
    if (jt == 0) {
        const float bo = sBo[0];
        #pragma unroll
        for (int s = 0; s < 4; s++) {
            float a, c; unpack2(y2[s], a, c);
            float2 o; o.x = a + bo; o.y = c + bo;
            *(float2*)(out + (size_t)t * NG + 2 * (G0 + ub + s)) = o;
        }
    }
}

__global__ void zero_head(float* __restrict__ out) {
    out[blockIdx.x * 256 + threadIdx.x] = 0.0f;
}

extern "C" void kernel_launch(void* const* d_in, const int* in_sizes, int n_in,
                              void* d_out, int out_size) {
    const float* x     = (const float*)d_in[0];
    const float* W_in  = (const float*)d_in[1];
    const float* b_in  = (const float*)d_in[2];
    const float* W_xh  = (const float*)d_in[3];
    const float* W_hh  = (const float*)d_in[4];
    const float* b_h   = (const float*)d_in[5];
    const float* W_out = (const float*)d_in[6];
    const float* b_out = (const float*)d_in[7];
    float* out = (float*)d_out;

    cudaFuncSetAttribute(narx_main, cudaFuncAttributeMaxDynamicSharedMemorySize,
                         SMEM_BYTES);

    zero_head<<<(DLY * NG) / 256, 256>>>(out);             // t < D rows = 0
    u_kernel<<<NT * 4, 256>>>(x, W_in, b_in);              // pack U
    narx_main<<<(NT - DLY) * 16, 128, SMEM_BYTES>>>(W_xh, W_hh, b_h,
                                                    W_out, b_out, out);
    (void)in_sizes; (void)n_in; (void)out_size;
}

// round 4
// speedup vs baseline: 5.5990x; 1.0440x over previous
#include <cuda_runtime.h>

// NARX RNN, D=4, HID=64, NX=16, NT=512, NGRID=2048, NY=1.
//
// R4: hoist the t-invariant part of each step out of the lag-window loop.
//   Z[tau] = relu(x[tau]·W_in + b_in)·W_xh + b_h      (kernel A, once per tau)
//   h_1 = tanh(Z[tau0]);  h_{d+1} = tanh(Z[tau_d] + h_d·W_hh)   (kernel B)
// This removes the 4x-redundant u·W_xh matvec from the recurrence: hot-loop
// fma2 per thread drops 14336 -> 6144.
//
// f32x2 lanes = adjacent-g sequence pair; weights come from smem tables where
// every scalar is pre-duplicated into a u64 splat -> one broadcast LDS.64 per
// weight operand, no splat MOVs in the inner loops.

typedef unsigned long long u64;

#define NT   512
#define NG   2048
#define NGP  1024      // g-pairs
#define NXF  16
#define DLY  4

__device__ u64 g_Z[(size_t)NT * 64 * NGP];   // 268 MB scratch: [tau][j][G]

__device__ __forceinline__ u64 fma2(u64 a, u64 b, u64 c) {
    u64 d; asm("fma.rn.f32x2 %0, %1, %2, %3;" : "=l"(d) : "l"(a), "l"(b), "l"(c));
    return d;
}
__device__ __forceinline__ u64 add2(u64 a, u64 b) {
    u64 d; asm("add.rn.f32x2 %0, %1, %2;" : "=l"(d) : "l"(a), "l"(b));
    return d;
}
__device__ __forceinline__ u64 pack2(float x) {
    u64 r; asm("mov.b64 %0, {%1, %1};" : "=l"(r) : "f"(x));
    return r;
}
__device__ __forceinline__ u64 pack2b(float a, float b) {
    u64 r; asm("mov.b64 %0, {%1, %2};" : "=l"(r) : "f"(a), "f"(b));
    return r;
}
__device__ __forceinline__ void unpack2(u64 v, float& lo, float& hi) {
    asm("mov.b64 {%0, %1}, %2;" : "=f"(lo), "=f"(hi) : "l"(v));
}
// tanh(x) = 1 - 2/(exp(2x)+1): MUFU.EX2 + MUFU.RCP, ~1e-6 rel err.
__device__ __forceinline__ float tanh_fast(float v) {
    float e = __expf(2.0f * v);
    return 1.0f - __fdividef(2.0f, e + 1.0f);
}

// ---------------- kernel A: Z[tau] = relu(x·W_in+b_in)·W_xh + b_h ----------
// One thread per (g-pair, j-half): acc = 32 u64. U[k] streamed (never stored).
__global__ __launch_bounds__(128)
void z_kernel(const float* __restrict__ x,
              const float* __restrict__ W_in, const float* __restrict__ b_in,
              const float* __restrict__ W_xh, const float* __restrict__ b_h)
{
    __shared__ u64 sWin2[NXF * 64];   //  8 KB, splat pairs
    __shared__ u64 sXh2[64 * 64];     // 32 KB, splat pairs
    __shared__ u64 sBin2[64];
    __shared__ u64 sBh2[64];

    const int tid = threadIdx.x;
    for (int i = tid; i < NXF * 64; i += 128) sWin2[i] = pack2(W_in[i]);
    for (int i = tid; i < 64 * 64;  i += 128) sXh2[i]  = pack2(W_xh[i]);
    if (tid < 64) { sBin2[tid] = pack2(b_in[tid]); sBh2[tid] = pack2(b_h[tid]); }
    __syncthreads();

    const int b   = blockIdx.x;             // 512 * 16 blocks
    const int tau = b >> 4;
    const int G   = ((b & 15) << 6) + (tid & 63);
    const int jh  = tid >> 6;               // j-half: owns j in [32jh, 32jh+32)

    // pack x rows g=2G, 2G+1 into 16 f32x2 pairs
    const float4* xr = (const float4*)(x + ((size_t)tau * NG + 2 * G) * NXF);
    float4 ra[4] = { xr[0], xr[1], xr[2], xr[3] };
    float4 rb[4] = { xr[4], xr[5], xr[6], xr[7] };
    const float* fa = (const float*)ra;
    const float* fb = (const float*)rb;
    u64 x2[16];
    #pragma unroll
    for (int i = 0; i < 16; i++) x2[i] = pack2b(fa[i], fb[i]);

    u64 acc[32];
    const u64* bh = sBh2 + jh * 32;
    #pragma unroll
    for (int jj = 0; jj < 32; jj++) acc[jj] = bh[jj];

    #pragma unroll 4
    for (int k = 0; k < 64; k++) {
        u64 up = sBin2[k];
        #pragma unroll
        for (int i = 0; i < 16; i++)
            up = fma2(x2[i], sWin2[i * 64 + k], up);
        float a, c; unpack2(up, a, c);
        up = pack2b(fmaxf(a, 0.0f), fmaxf(c, 0.0f));      // relu
        const u64* w = sXh2 + k * 64 + jh * 32;
        #pragma unroll
        for (int jj = 0; jj < 32; jj++)
            acc[jj] = fma2(up, w[jj], acc[jj]);
    }

    u64* dst = g_Z + ((size_t)tau * 64 + jh * 32) * NGP + G;
    #pragma unroll
    for (int jj = 0; jj < 32; jj++) dst[(size_t)jj * NGP] = acc[jj];
}

// ---------------- kernel B: recurrence over the lag window ----------------
// Dynamic smem (bytes):
//   [0, 34304)       sH   : u64 [64 units][67]  (padded)
//   [34304, 67072)   sHh2 : u64 [64][64]  W_hh splat pairs (32 KB)
//   [67072, 67584)   sWo2 : u64 [64]      W_out splat pairs
//   [67584, 67588)   sBo  : float
#define SMEM_BYTES 67592

__global__ __launch_bounds__(128, 3)
void narx_main(const float* __restrict__ W_hh, const float* __restrict__ W_out,
               const float* __restrict__ b_out, float* __restrict__ out)
{
    extern __shared__ char smem[];
    u64*   sH   = (u64*)smem;
    u64*   sHh2 = (u64*)(smem + 34304);
    u64*   sWo2 = (u64*)(smem + 67072);
    float* sBo  = (float*)(smem + 67584);

    const int tid = threadIdx.x;
    for (int i = tid; i < 4096; i += 128) sHh2[i] = pack2(W_hh[i]);
    if (tid < 64) sWo2[tid] = pack2(W_out[tid]);
    if (tid == 0) sBo[0] = b_out[0];
    __syncthreads();

    const int b   = blockIdx.x;          // 508*16 blocks
    const int t   = DLY + (b >> 4);      // uniform per block
    const int G0  = (b & 15) << 6;       // 64 g-pair units per block
    const int jt  = tid & 7;             // owns j == jt (mod 8)
    const int grp = tid >> 3;            // 0..15
    const int ub  = grp << 2;            // group's unit base (4 units)

    u64* hr0 = sH + (size_t)(ub + 0) * 67;
    u64* hr1 = sH + (size_t)(ub + 1) * 67;
    u64* hr2 = sH + (size_t)(ub + 2) * 67;
    u64* hr3 = sH + (size_t)(ub + 3) * 67;

    u64 acc[4][8];
    u64 y2[4] = {0ull, 0ull, 0ull, 0ull};

    // ---- d = 0:  h = tanh(Z[tau0]) ----
    {
        const int tau = t - DLY;
        #pragma unroll
        for (int jj = 0; jj < 8; jj++) {
            const int j = (jj << 3) + jt;
            const u64* zp = g_Z + ((size_t)tau * 64 + j) * NGP + (G0 + ub);
            const ulonglong2 za = *(const ulonglong2*)zp;
            const ulonglong2 zb = *(const ulonglong2*)(zp + 2);
            float a, c;
            unpack2(za.x, a, c); hr0[j] = pack2b(tanh_fast(a), tanh_fast(c));
            unpack2(za.y, a, c); hr1[j] = pack2b(tanh_fast(a), tanh_fast(c));
            unpack2(zb.x, a, c); hr2[j] = pack2b(tanh_fast(a), tanh_fast(c));
            unpack2(zb.y, a, c); hr3[j] = pack2b(tanh_fast(a), tanh_fast(c));
        }
    }
    __syncwarp();

    // ---- d = 1..3:  h = tanh(Z[tau] + h·W_hh) ----
    for (int d = 1; d < DLY; d++) {
        const int tau = t - DLY + d;

        #pragma unroll
        for (int jj = 0; jj < 8; jj++) {
            const int j = (jj << 3) + jt;
            const u64* zp = g_Z + ((size_t)tau * 64 + j) * NGP + (G0 + ub);
            const ulonglong2 za = *(const ulonglong2*)zp;
            const ulonglong2 zb = *(const ulonglong2*)(zp + 2);
            acc[0][jj] = za.x; acc[1][jj] = za.y;
            acc[2][jj] = zb.x; acc[3][jj] = zb.y;
        }

        const u64* wp = sHh2 + jt;
        #pragma unroll 1
        for (int k0 = 0; k0 < 64; k0 += 8) {
            #pragma unroll
            for (int kk = 0; kk < 8; kk++) {
                const int k = k0 + kk;
                const u64 h0 = hr0[k], h1 = hr1[k], h2 = hr2[k], h3 = hr3[k];
                const u64* w = wp + (k << 6);
                #pragma unroll
                for (int jj = 0; jj < 8; jj++) {
                    const u64 w2 = w[jj << 3];     // splat pair, broadcast LDS.64
                    acc[0][jj] = fma2(h0, w2, acc[0][jj]);
                    acc[1][jj] = fma2(h1, w2, acc[1][jj]);
                    acc[2][jj] = fma2(h2, w2, acc[2][jj]);
                    acc[3][jj] = fma2(h3, w2, acc[3][jj]);
                }
            }
        }

        __syncwarp();   // done READING old h before overwriting

        if (d < DLY - 1) {
            #pragma unroll
            for (int s = 0; s < 4; s++) {
                u64* hrs = sH + (size_t)(ub + s) * 67;
                #pragma unroll
                for (int jj = 0; jj < 8; jj++) {
                    float a, c; unpack2(acc[s][jj], a, c);
                    hrs[(jj << 3) + jt] = pack2b(tanh_fast(a), tanh_fast(c));
                }
            }
        } else {
            // fold tanh of the final h straight into the output dot product
            #pragma unroll
            for (int s = 0; s < 4; s++) {
                #pragma unroll
                for (int jj = 0; jj < 8; jj++) {
                    float a, c; unpack2(acc[s][jj], a, c);
                    const u64 hp = pack2b(tanh_fast(a), tanh_fast(c));
                    y2[s] = fma2(hp, sWo2[(jj << 3) + jt], y2[s]);
                }
            }
        }
        __syncwarp();   // new h visible before next step
    }

    // reduce over the 8 jt lanes, store 2 floats per unit
    #pragma unroll
    for (int s = 0; s < 4; s++) {
        u64 v = y2[s];
        v = add2(v, __shfl_xor_sync(0xFFFFFFFFu, v, 1));
        v = add2(v, __shfl_xor_sync(0xFFFFFFFFu, v, 2));
        v = add2(v, __shfl_xor_sync(0xFFFFFFFFu, v, 4));
        y2[s] = v;
    }
    if (jt == 0) {
        const float bo = sBo[0];
        #pragma unroll
        for (int s = 0; s < 4; s++) {
            float a, c; unpack2(y2[s], a, c);
            float2 o; o.x = a + bo; o.y = c + bo;
            *(float2*)(out + (size_t)t * NG + 2 * (G0 + ub + s)) = o;
        }
    }
}

__global__ void zero_head(float* __restrict__ out) {
    out[blockIdx.x * 256 + threadIdx.x] = 0.0f;
}

extern "C" void kernel_launch(void* const* d_in, const int* in_sizes, int n_in,
                              void* d_out, int out_size) {
    const float* x     = (const float*)d_in[0];
    const float* W_in  = (const float*)d_in[1];
    const float* b_in  = (const float*)d_in[2];
    const float* W_xh  = (const float*)d_in[3];
    const float* W_hh  = (const float*)d_in[4];
    const float* b_h   = (const float*)d_in[5];
    const float* W_out = (const float*)d_in[6];
    const float* b_out = (const float*)d_in[7];
    float* out = (float*)d_out;

    cudaFuncSetAttribute(narx_main, cudaFuncAttributeMaxDynamicSharedMemorySize,
                         SMEM_BYTES);

    zero_head<<<(DLY * NG) / 256, 256>>>(out);                  // t < D rows
    z_kernel<<<NT * 16, 128>>>(x, W_in, b_in, W_xh, b_h);       // Z per tau
    narx_main<<<(NT - DLY) * 16, 128, SMEM_BYTES>>>(W_hh, W_out, b_out, out);
    (void)in_sizes; (void)n_in; (void)out_size;
}